// round 1
// baseline (speedup 1.0000x reference)
#include <cuda_runtime.h>

#define NMAX 100000
#define HID 64

// ---------------- scratch (device globals, no allocation) ----------------
__device__ float g_h0[NMAX * HID];     // fc output
__device__ float g_hs[NMAX * HID];     // pre-scaled messages (h@w)*norm_out
__device__ float g_agg[NMAX * HID];    // scatter-add accumulator
__device__ float g_h1[NMAX * HID];     // layer-1 output (residual input for layer 2)
__device__ int   g_deg_out[NMAX];
__device__ int   g_deg_in[NMAX];
__device__ float g_norm_out[NMAX];
__device__ float g_norm_in[NMAX];
__device__ float g_stats[2 * HID];     // [0:64) sum, [64:128) sumsq

__device__ __forceinline__ float scale_const() { return 0.70710678118654752440f; }

// ---------------- zeroing ----------------
__global__ void zero_all_kernel(int n_nodes) {
    int idx = blockIdx.x * blockDim.x + threadIdx.x;
    int agg4 = n_nodes * 16;
    if (idx < agg4) reinterpret_cast<float4*>(g_agg)[idx] = make_float4(0.f, 0.f, 0.f, 0.f);
    if (idx < n_nodes) { g_deg_out[idx] = 0; g_deg_in[idx] = 0; }
    if (idx < 2 * HID) g_stats[idx] = 0.f;
}

__global__ void zero_agg_kernel(int n_nodes) {
    int idx = blockIdx.x * blockDim.x + threadIdx.x;
    if (idx < n_nodes * 16) reinterpret_cast<float4*>(g_agg)[idx] = make_float4(0.f, 0.f, 0.f, 0.f);
}

// ---------------- degrees & norms ----------------
__global__ void degree_kernel(const int* __restrict__ src, const int* __restrict__ dst, int n_edges) {
    int e = blockIdx.x * blockDim.x + threadIdx.x;
    if (e < n_edges) {
        atomicAdd(&g_deg_out[src[e]], 1);
        atomicAdd(&g_deg_in[dst[e]], 1);
    }
}

__global__ void norm_kernel(int n_nodes) {
    int n = blockIdx.x * blockDim.x + threadIdx.x;
    if (n < n_nodes) {
        int dov = g_deg_out[n]; if (dov < 1) dov = 1;
        int div_ = g_deg_in[n]; if (div_ < 1) div_ = 1;
        g_norm_out[n] = rsqrtf((float)dov);
        g_norm_in[n]  = rsqrtf((float)div_);
    }
}

// ---------------- fc GEMM: h0 = x @ fc_w + fc_b  (K=128 -> 64) ----------------
__global__ __launch_bounds__(256) void fc_kernel(const float* __restrict__ x,
                                                 const float* __restrict__ w,
                                                 const float* __restrict__ b,
                                                 int n_nodes) {
    __shared__ float sA[64][68];
    __shared__ float sW[64][64];
    int br = blockIdx.x * 64;
    int tx = threadIdx.x & 15, ty = threadIdx.x >> 4;
    int r0 = ty * 4, j0 = tx * 4;
    float4 acc[4];
    acc[0] = acc[1] = acc[2] = acc[3] = make_float4(0.f, 0.f, 0.f, 0.f);

    for (int kc = 0; kc < 2; kc++) {
        if (kc) __syncthreads();
        // load W chunk [64][64]
        for (int i = threadIdx.x; i < 1024; i += 256) {
            int k = i >> 4, c = (i & 15) << 2;
            *(float4*)&sW[k][c] = *(const float4*)&w[(kc * 64 + k) * 64 + c];
        }
        // load x tile [64 rows][64 k]
        for (int i = threadIdx.x; i < 1024; i += 256) {
            int r = i >> 4, c4 = i & 15;
            int row = br + r;
            float4 v = make_float4(0.f, 0.f, 0.f, 0.f);
            if (row < n_nodes) v = *(const float4*)&x[row * 128 + kc * 64 + (c4 << 2)];
            *(float4*)&sA[r][c4 << 2] = v;
        }
        __syncthreads();
        #pragma unroll 16
        for (int k = 0; k < 64; k++) {
            float4 wv = *(float4*)&sW[k][j0];
            #pragma unroll
            for (int i = 0; i < 4; i++) {
                float a = sA[r0 + i][k];
                acc[i].x = fmaf(a, wv.x, acc[i].x);
                acc[i].y = fmaf(a, wv.y, acc[i].y);
                acc[i].z = fmaf(a, wv.z, acc[i].z);
                acc[i].w = fmaf(a, wv.w, acc[i].w);
            }
        }
    }
    float4 bv = *(const float4*)&b[j0];
    #pragma unroll
    for (int i = 0; i < 4; i++) {
        int row = br + r0 + i;
        if (row < n_nodes) {
            float4 o;
            o.x = acc[i].x + bv.x; o.y = acc[i].y + bv.y;
            o.z = acc[i].z + bv.z; o.w = acc[i].w + bv.w;
            *(float4*)&g_h0[row * 64 + j0] = o;
        }
    }
}

// ---------------- gemm1: hs = (h0 @ w1) * norm_out[n]  (K=64) ----------------
__global__ __launch_bounds__(256) void gemm1_kernel(const float* __restrict__ w1, int n_nodes) {
    __shared__ float sA[64][68];
    __shared__ float sW[64][64];
    int br = blockIdx.x * 64;
    int tx = threadIdx.x & 15, ty = threadIdx.x >> 4;
    int r0 = ty * 4, j0 = tx * 4;

    for (int i = threadIdx.x; i < 1024; i += 256) {
        int k = i >> 4, c = (i & 15) << 2;
        *(float4*)&sW[k][c] = *(const float4*)&w1[k * 64 + c];
    }
    for (int i = threadIdx.x; i < 1024; i += 256) {
        int r = i >> 4, c4 = i & 15;
        int row = br + r;
        float4 v = make_float4(0.f, 0.f, 0.f, 0.f);
        if (row < n_nodes) v = *(const float4*)&g_h0[row * 64 + (c4 << 2)];
        *(float4*)&sA[r][c4 << 2] = v;
    }
    __syncthreads();

    float4 acc[4];
    acc[0] = acc[1] = acc[2] = acc[3] = make_float4(0.f, 0.f, 0.f, 0.f);
    #pragma unroll 16
    for (int k = 0; k < 64; k++) {
        float4 wv = *(float4*)&sW[k][j0];
        #pragma unroll
        for (int i = 0; i < 4; i++) {
            float a = sA[r0 + i][k];
            acc[i].x = fmaf(a, wv.x, acc[i].x);
            acc[i].y = fmaf(a, wv.y, acc[i].y);
            acc[i].z = fmaf(a, wv.z, acc[i].z);
            acc[i].w = fmaf(a, wv.w, acc[i].w);
        }
    }
    #pragma unroll
    for (int i = 0; i < 4; i++) {
        int row = br + r0 + i;
        if (row < n_nodes) {
            float ns = g_norm_out[row];
            float4 o;
            o.x = acc[i].x * ns; o.y = acc[i].y * ns;
            o.z = acc[i].z * ns; o.w = acc[i].w * ns;
            *(float4*)&g_hs[row * 64 + j0] = o;
        }
    }
}

// ---------------- edge scatter: agg[dst] += hs[src] ----------------
__global__ __launch_bounds__(256) void edge_kernel(const int* __restrict__ src,
                                                   const int* __restrict__ dst,
                                                   int n_edges) {
    int idx = blockIdx.x * blockDim.x + threadIdx.x;
    if (idx >= n_edges * 16) return;
    int e = idx >> 4, c = idx & 15;
    int s = src[e], d = dst[e];
    float4 v = reinterpret_cast<const float4*>(g_hs)[s * 16 + c];
    float* a = &g_agg[d * 64 + (c << 2)];
    atomicAdd(a + 0, v.x);
    atomicAdd(a + 1, v.y);
    atomicAdd(a + 2, v.z);
    atomicAdd(a + 3, v.w);
}

// ---------------- fused layer-1 epilogue + gemm2 ----------------
// h1 = (h0 + agg*norm_in + b1)*SCALE  (stored);  hs = (h1 @ w2) * norm_out
__global__ __launch_bounds__(256) void gemm2_fused_kernel(const float* __restrict__ b1,
                                                          const float* __restrict__ w2,
                                                          int n_nodes) {
    __shared__ float sA[64][68];
    __shared__ float sW[64][64];
    int br = blockIdx.x * 64;
    int tx = threadIdx.x & 15, ty = threadIdx.x >> 4;
    int r0 = ty * 4, j0 = tx * 4;
    const float sc = scale_const();

    for (int i = threadIdx.x; i < 1024; i += 256) {
        int k = i >> 4, c = (i & 15) << 2;
        *(float4*)&sW[k][c] = *(const float4*)&w2[k * 64 + c];
    }
    for (int i = threadIdx.x; i < 1024; i += 256) {
        int r = i >> 4, c4 = i & 15;
        int row = br + r;
        float4 v = make_float4(0.f, 0.f, 0.f, 0.f);
        if (row < n_nodes) {
            float4 h0v = *(const float4*)&g_h0[row * 64 + (c4 << 2)];
            float4 ag  = *(const float4*)&g_agg[row * 64 + (c4 << 2)];
            float  ni  = g_norm_in[row];
            float4 bv  = *(const float4*)&b1[(c4 << 2)];
            v.x = (h0v.x + ag.x * ni + bv.x) * sc;
            v.y = (h0v.y + ag.y * ni + bv.y) * sc;
            v.z = (h0v.z + ag.z * ni + bv.z) * sc;
            v.w = (h0v.w + ag.w * ni + bv.w) * sc;
            *(float4*)&g_h1[row * 64 + (c4 << 2)] = v;
        }
        *(float4*)&sA[r][c4 << 2] = v;
    }
    __syncthreads();

    float4 acc[4];
    acc[0] = acc[1] = acc[2] = acc[3] = make_float4(0.f, 0.f, 0.f, 0.f);
    #pragma unroll 16
    for (int k = 0; k < 64; k++) {
        float4 wv = *(float4*)&sW[k][j0];
        #pragma unroll
        for (int i = 0; i < 4; i++) {
            float a = sA[r0 + i][k];
            acc[i].x = fmaf(a, wv.x, acc[i].x);
            acc[i].y = fmaf(a, wv.y, acc[i].y);
            acc[i].z = fmaf(a, wv.z, acc[i].z);
            acc[i].w = fmaf(a, wv.w, acc[i].w);
        }
    }
    #pragma unroll
    for (int i = 0; i < 4; i++) {
        int row = br + r0 + i;
        if (row < n_nodes) {
            float ns = g_norm_out[row];
            float4 o;
            o.x = acc[i].x * ns; o.y = acc[i].y * ns;
            o.z = acc[i].z * ns; o.w = acc[i].w * ns;
            *(float4*)&g_hs[row * 64 + j0] = o;
        }
    }
}

// ---------------- layer-2 epilogue + BN statistics ----------------
// h2 = (h1 + agg*norm_in + b2)*SCALE -> out; accumulate per-feature sum & sumsq
__global__ __launch_bounds__(256) void stats_kernel(const float* __restrict__ b2,
                                                    float* __restrict__ out,
                                                    int n_nodes) {
    int total = n_nodes * 64;
    int j = threadIdx.x & 63;
    float bj = b2[j];
    const float sc = scale_const();
    float s = 0.f, sq = 0.f;
    int stride = gridDim.x * 256;
    for (int idx = blockIdx.x * 256 + threadIdx.x; idx < total; idx += stride) {
        int row = idx >> 6;
        float v = (g_h1[idx] + g_agg[idx] * g_norm_in[row] + bj) * sc;
        out[idx] = v;
        s += v; sq += v * v;
    }
    __shared__ float ssum[64], ssq[64];
    if (threadIdx.x < 64) { ssum[threadIdx.x] = 0.f; ssq[threadIdx.x] = 0.f; }
    __syncthreads();
    atomicAdd(&ssum[j], s);
    atomicAdd(&ssq[j], sq);
    __syncthreads();
    if (threadIdx.x < 64) {
        atomicAdd(&g_stats[threadIdx.x], ssum[threadIdx.x]);
        atomicAdd(&g_stats[64 + threadIdx.x], ssq[threadIdx.x]);
    }
}

// ---------------- BN apply ----------------
__global__ __launch_bounds__(256) void bn_kernel(float* __restrict__ out,
                                                 const float* __restrict__ gamma,
                                                 const float* __restrict__ beta,
                                                 int n_nodes) {
    __shared__ float s_scale[64], s_shift[64];
    if (threadIdx.x < 64) {
        int j = threadIdx.x;
        float inv_n = 1.f / (float)n_nodes;
        float mu = g_stats[j] * inv_n;
        float var = g_stats[64 + j] * inv_n - mu * mu;
        if (var < 0.f) var = 0.f;
        float g = rsqrtf(var + 1e-5f) * gamma[j];
        s_scale[j] = g;
        s_shift[j] = beta[j] - mu * g;
    }
    __syncthreads();
    int total4 = n_nodes * 16;
    int stride = gridDim.x * blockDim.x;
    for (int i = blockIdx.x * blockDim.x + threadIdx.x; i < total4; i += stride) {
        float4 v = reinterpret_cast<float4*>(out)[i];
        int j0 = (i & 15) << 2;
        v.x = v.x * s_scale[j0 + 0] + s_shift[j0 + 0];
        v.y = v.y * s_scale[j0 + 1] + s_shift[j0 + 1];
        v.z = v.z * s_scale[j0 + 2] + s_shift[j0 + 2];
        v.w = v.w * s_scale[j0 + 3] + s_shift[j0 + 3];
        reinterpret_cast<float4*>(out)[i] = v;
    }
}

// ---------------- launch ----------------
extern "C" void kernel_launch(void* const* d_in, const int* in_sizes, int n_in,
                              void* d_out, int out_size) {
    const int*   src   = (const int*)d_in[0];
    const int*   dst   = (const int*)d_in[1];
    const float* x     = (const float*)d_in[2];
    const float* fc_w  = (const float*)d_in[3];
    const float* fc_b  = (const float*)d_in[4];
    const float* w1    = (const float*)d_in[5];
    const float* b1    = (const float*)d_in[6];
    const float* w2    = (const float*)d_in[7];
    const float* b2    = (const float*)d_in[8];
    const float* gamma = (const float*)d_in[9];
    const float* beta  = (const float*)d_in[10];
    float* out = (float*)d_out;

    int n_edges = in_sizes[0];
    int n_nodes = in_sizes[2] / 128;

    int z_threads = n_nodes * 16;
    zero_all_kernel<<<(z_threads + 255) / 256, 256>>>(n_nodes);
    degree_kernel<<<(n_edges + 255) / 256, 256>>>(src, dst, n_edges);
    norm_kernel<<<(n_nodes + 255) / 256, 256>>>(n_nodes);

    int gblocks = (n_nodes + 63) / 64;
    fc_kernel<<<gblocks, 256>>>(x, fc_w, fc_b, n_nodes);

    // layer 1
    gemm1_kernel<<<gblocks, 256>>>(w1, n_nodes);
    edge_kernel<<<(n_edges * 16 + 255) / 256, 256>>>(src, dst, n_edges);

    // layer 2 (fused layer-1 epilogue + gemm), re-zero accumulator, scatter
    gemm2_fused_kernel<<<gblocks, 256>>>(b1, w2, n_nodes);
    zero_agg_kernel<<<(n_nodes * 16 + 255) / 256, 256>>>(n_nodes);
    edge_kernel<<<(n_edges * 16 + 255) / 256, 256>>>(src, dst, n_edges);

    // epilogue + batch-norm
    stats_kernel<<<512, 256>>>(b2, out, n_nodes);
    bn_kernel<<<512, 256>>>(out, gamma, beta, n_nodes);
}

// round 2
// speedup vs baseline: 1.8136x; 1.8136x over previous
#include <cuda_runtime.h>

#define NMAX 100000
#define EMAX 800000
#define HID 64

// ---------------- scratch (device globals) ----------------
__device__ float g_h0[NMAX * HID];
__device__ float g_hs[NMAX * HID];
__device__ float g_agg[NMAX * HID];     // layer-1 aggregation (norm_in folded)
__device__ float g_h1[NMAX * HID];
__device__ int   g_deg_out[NMAX];
__device__ int   g_deg_in[NMAX];
__device__ float g_norm_out[NMAX];
__device__ float g_norm_in[NMAX];
__device__ int   g_incl[NMAX];
__device__ int   g_blocksum[128];
__device__ int   g_blockoff[128];
__device__ int   g_rowstart[NMAX];
__device__ int   g_cursor[NMAX];
__device__ int   g_csr_src[EMAX];
__device__ float g_stats[2 * HID];

__device__ __forceinline__ float scale_const() { return 0.70710678118654752440f; }

// ---------------- init ----------------
__global__ void zero_all_kernel(int n_nodes) {
    int idx = blockIdx.x * blockDim.x + threadIdx.x;
    if (idx < n_nodes) { g_deg_out[idx] = 0; g_deg_in[idx] = 0; }
    if (idx < 2 * HID) g_stats[idx] = 0.f;
}

__global__ void degree_kernel(const int* __restrict__ src, const int* __restrict__ dst, int n_edges) {
    int e = blockIdx.x * blockDim.x + threadIdx.x;
    if (e < n_edges) {
        atomicAdd(&g_deg_out[src[e]], 1);
        atomicAdd(&g_deg_in[dst[e]], 1);
    }
}

// ---------------- CSR build: scan of deg_in ----------------
__global__ __launch_bounds__(1024) void scan_block_kernel(int n_nodes) {
    __shared__ int sh[1024];
    int gid = blockIdx.x * 1024 + threadIdx.x;
    int v = (gid < n_nodes) ? g_deg_in[gid] : 0;
    sh[threadIdx.x] = v;
    __syncthreads();
    for (int off = 1; off < 1024; off <<= 1) {
        int t = 0;
        if (threadIdx.x >= off) t = sh[threadIdx.x - off];
        __syncthreads();
        if (threadIdx.x >= off) sh[threadIdx.x] += t;
        __syncthreads();
    }
    if (gid < n_nodes) g_incl[gid] = sh[threadIdx.x];
    if (threadIdx.x == 1023) g_blocksum[blockIdx.x] = sh[1023];
}

__global__ void scan_spine_kernel(int n_blocks) {
    if (threadIdx.x == 0 && blockIdx.x == 0) {
        int running = 0;
        for (int i = 0; i < n_blocks; i++) {
            g_blockoff[i] = running;
            running += g_blocksum[i];
        }
    }
}

__global__ void finalize_kernel(int n_nodes) {
    int n = blockIdx.x * blockDim.x + threadIdx.x;
    if (n < n_nodes) {
        int deg = g_deg_in[n];
        int incl = g_incl[n] + g_blockoff[n >> 10];
        int start = incl - deg;
        g_rowstart[n] = start;
        g_cursor[n] = start;
        int dov = g_deg_out[n]; if (dov < 1) dov = 1;
        int din = deg; if (din < 1) din = 1;
        g_norm_out[n] = rsqrtf((float)dov);
        g_norm_in[n]  = rsqrtf((float)din);
    }
}

__global__ void bin_kernel(const int* __restrict__ src, const int* __restrict__ dst, int n_edges) {
    int e = blockIdx.x * blockDim.x + threadIdx.x;
    if (e < n_edges) {
        int p = atomicAdd(&g_cursor[dst[e]], 1);
        g_csr_src[p] = src[e];
    }
}

// ---------------- fc GEMM: h0 = x @ fc_w + fc_b  (K=128) ----------------
// 128-row tile, 256 threads, 8x4 micro-tile
__global__ __launch_bounds__(256) void fc_kernel(const float* __restrict__ x,
                                                 const float* __restrict__ w,
                                                 const float* __restrict__ b,
                                                 int n_nodes) {
    __shared__ float sA[128][68];
    __shared__ float sW[64][64];
    int br = blockIdx.x * 128;
    int tx = threadIdx.x & 15, ty = threadIdx.x >> 4;
    int r0 = ty * 8, j0 = tx * 4;
    float4 acc[8];
    #pragma unroll
    for (int i = 0; i < 8; i++) acc[i] = make_float4(0.f, 0.f, 0.f, 0.f);

    for (int kc = 0; kc < 2; kc++) {
        if (kc) __syncthreads();
        for (int i = threadIdx.x; i < 1024; i += 256) {
            int k = i >> 4, c = (i & 15) << 2;
            *(float4*)&sW[k][c] = *(const float4*)&w[(kc * 64 + k) * 64 + c];
        }
        for (int i = threadIdx.x; i < 2048; i += 256) {
            int r = i >> 4, c4 = i & 15;
            int row = br + r;
            float4 v = make_float4(0.f, 0.f, 0.f, 0.f);
            if (row < n_nodes) v = *(const float4*)&x[row * 128 + kc * 64 + (c4 << 2)];
            *(float4*)&sA[r][c4 << 2] = v;
        }
        __syncthreads();
        #pragma unroll 8
        for (int k = 0; k < 64; k++) {
            float4 wv = *(float4*)&sW[k][j0];
            #pragma unroll
            for (int i = 0; i < 8; i++) {
                float a = sA[r0 + i][k];
                acc[i].x = fmaf(a, wv.x, acc[i].x);
                acc[i].y = fmaf(a, wv.y, acc[i].y);
                acc[i].z = fmaf(a, wv.z, acc[i].z);
                acc[i].w = fmaf(a, wv.w, acc[i].w);
            }
        }
    }
    float4 bv = *(const float4*)&b[j0];
    #pragma unroll
    for (int i = 0; i < 8; i++) {
        int row = br + r0 + i;
        if (row < n_nodes) {
            float4 o;
            o.x = acc[i].x + bv.x; o.y = acc[i].y + bv.y;
            o.z = acc[i].z + bv.z; o.w = acc[i].w + bv.w;
            *(float4*)&g_h0[row * 64 + j0] = o;
        }
    }
}

// ---------------- gemm1: hs = (h0 @ w1) * norm_out  (K=64) ----------------
__global__ __launch_bounds__(256) void gemm1_kernel(const float* __restrict__ w1, int n_nodes) {
    __shared__ float sA[128][68];
    __shared__ float sW[64][64];
    int br = blockIdx.x * 128;
    int tx = threadIdx.x & 15, ty = threadIdx.x >> 4;
    int r0 = ty * 8, j0 = tx * 4;

    for (int i = threadIdx.x; i < 1024; i += 256) {
        int k = i >> 4, c = (i & 15) << 2;
        *(float4*)&sW[k][c] = *(const float4*)&w1[k * 64 + c];
    }
    for (int i = threadIdx.x; i < 2048; i += 256) {
        int r = i >> 4, c4 = i & 15;
        int row = br + r;
        float4 v = make_float4(0.f, 0.f, 0.f, 0.f);
        if (row < n_nodes) v = *(const float4*)&g_h0[row * 64 + (c4 << 2)];
        *(float4*)&sA[r][c4 << 2] = v;
    }
    __syncthreads();

    float4 acc[8];
    #pragma unroll
    for (int i = 0; i < 8; i++) acc[i] = make_float4(0.f, 0.f, 0.f, 0.f);
    #pragma unroll 8
    for (int k = 0; k < 64; k++) {
        float4 wv = *(float4*)&sW[k][j0];
        #pragma unroll
        for (int i = 0; i < 8; i++) {
            float a = sA[r0 + i][k];
            acc[i].x = fmaf(a, wv.x, acc[i].x);
            acc[i].y = fmaf(a, wv.y, acc[i].y);
            acc[i].z = fmaf(a, wv.z, acc[i].z);
            acc[i].w = fmaf(a, wv.w, acc[i].w);
        }
    }
    #pragma unroll
    for (int i = 0; i < 8; i++) {
        int row = br + r0 + i;
        if (row < n_nodes) {
            float ns = g_norm_out[row];
            float4 o;
            o.x = acc[i].x * ns; o.y = acc[i].y * ns;
            o.z = acc[i].z * ns; o.w = acc[i].w * ns;
            *(float4*)&g_hs[row * 64 + j0] = o;
        }
    }
}

// ---------------- layer-1 aggregation (gather, no atomics) ----------------
// agg[n] = norm_in[n] * sum_{e in CSR[n]} hs[src_e]
__global__ __launch_bounds__(256) void agg1_kernel(int n_nodes) {
    int node = blockIdx.x * 16 + (threadIdx.x >> 4);
    int c = threadIdx.x & 15;
    if (node >= n_nodes) return;
    int beg = g_rowstart[node];
    int end = beg + g_deg_in[node];
    float4 acc = make_float4(0.f, 0.f, 0.f, 0.f);
    for (int e = beg; e < end; e++) {
        int s = g_csr_src[e];
        float4 v = reinterpret_cast<const float4*>(g_hs)[s * 16 + c];
        acc.x += v.x; acc.y += v.y; acc.z += v.z; acc.w += v.w;
    }
    float ni = g_norm_in[node];
    float4 o;
    o.x = acc.x * ni; o.y = acc.y * ni; o.z = acc.z * ni; o.w = acc.w * ni;
    reinterpret_cast<float4*>(g_agg)[node * 16 + c] = o;
}

// ---------------- fused layer-1 epilogue + gemm2 ----------------
// h1 = (h0 + agg + b1)*SCALE  (agg already has norm_in);  hs = (h1 @ w2)*norm_out
__global__ __launch_bounds__(256) void gemm2_fused_kernel(const float* __restrict__ b1,
                                                          const float* __restrict__ w2,
                                                          int n_nodes) {
    __shared__ float sA[128][68];
    __shared__ float sW[64][64];
    int br = blockIdx.x * 128;
    int tx = threadIdx.x & 15, ty = threadIdx.x >> 4;
    int r0 = ty * 8, j0 = tx * 4;
    const float sc = scale_const();

    for (int i = threadIdx.x; i < 1024; i += 256) {
        int k = i >> 4, c = (i & 15) << 2;
        *(float4*)&sW[k][c] = *(const float4*)&w2[k * 64 + c];
    }
    for (int i = threadIdx.x; i < 2048; i += 256) {
        int r = i >> 4, c4 = i & 15;
        int row = br + r;
        float4 v = make_float4(0.f, 0.f, 0.f, 0.f);
        if (row < n_nodes) {
            float4 h0v = *(const float4*)&g_h0[row * 64 + (c4 << 2)];
            float4 ag  = *(const float4*)&g_agg[row * 64 + (c4 << 2)];
            float4 bv  = *(const float4*)&b1[(c4 << 2)];
            v.x = (h0v.x + ag.x + bv.x) * sc;
            v.y = (h0v.y + ag.y + bv.y) * sc;
            v.z = (h0v.z + ag.z + bv.z) * sc;
            v.w = (h0v.w + ag.w + bv.w) * sc;
            *(float4*)&g_h1[row * 64 + (c4 << 2)] = v;
        }
        *(float4*)&sA[r][c4 << 2] = v;
    }
    __syncthreads();

    float4 acc[8];
    #pragma unroll
    for (int i = 0; i < 8; i++) acc[i] = make_float4(0.f, 0.f, 0.f, 0.f);
    #pragma unroll 8
    for (int k = 0; k < 64; k++) {
        float4 wv = *(float4*)&sW[k][j0];
        #pragma unroll
        for (int i = 0; i < 8; i++) {
            float a = sA[r0 + i][k];
            acc[i].x = fmaf(a, wv.x, acc[i].x);
            acc[i].y = fmaf(a, wv.y, acc[i].y);
            acc[i].z = fmaf(a, wv.z, acc[i].z);
            acc[i].w = fmaf(a, wv.w, acc[i].w);
        }
    }
    #pragma unroll
    for (int i = 0; i < 8; i++) {
        int row = br + r0 + i;
        if (row < n_nodes) {
            float ns = g_norm_out[row];
            float4 o;
            o.x = acc[i].x * ns; o.y = acc[i].y * ns;
            o.z = acc[i].z * ns; o.w = acc[i].w * ns;
            *(float4*)&g_hs[row * 64 + j0] = o;
        }
    }
}

// ---------------- fused layer-2 aggregation + epilogue + BN stats ----------------
__global__ __launch_bounds__(256) void agg2_stats_kernel(const float* __restrict__ b2,
                                                         float* __restrict__ out,
                                                         int n_nodes) {
    __shared__ float ssum[64], ssq[64];
    if (threadIdx.x < 64) { ssum[threadIdx.x] = 0.f; ssq[threadIdx.x] = 0.f; }
    __syncthreads();
    int c = threadIdx.x & 15;
    float4 bv = reinterpret_cast<const float4*>(b2)[c];
    const float sc = scale_const();
    float4 ls = make_float4(0.f, 0.f, 0.f, 0.f);
    float4 lq = make_float4(0.f, 0.f, 0.f, 0.f);

    for (int node = blockIdx.x * 16 + (threadIdx.x >> 4); node < n_nodes; node += gridDim.x * 16) {
        int beg = g_rowstart[node];
        int end = beg + g_deg_in[node];
        float4 acc = make_float4(0.f, 0.f, 0.f, 0.f);
        for (int e = beg; e < end; e++) {
            int s = g_csr_src[e];
            float4 v = reinterpret_cast<const float4*>(g_hs)[s * 16 + c];
            acc.x += v.x; acc.y += v.y; acc.z += v.z; acc.w += v.w;
        }
        float ni = g_norm_in[node];
        float4 h1v = reinterpret_cast<const float4*>(g_h1)[node * 16 + c];
        float4 h2;
        h2.x = (h1v.x + acc.x * ni + bv.x) * sc;
        h2.y = (h1v.y + acc.y * ni + bv.y) * sc;
        h2.z = (h1v.z + acc.z * ni + bv.z) * sc;
        h2.w = (h1v.w + acc.w * ni + bv.w) * sc;
        reinterpret_cast<float4*>(out)[node * 16 + c] = h2;
        ls.x += h2.x; ls.y += h2.y; ls.z += h2.z; ls.w += h2.w;
        lq.x += h2.x * h2.x; lq.y += h2.y * h2.y; lq.z += h2.z * h2.z; lq.w += h2.w * h2.w;
    }
    atomicAdd(&ssum[c * 4 + 0], ls.x); atomicAdd(&ssq[c * 4 + 0], lq.x);
    atomicAdd(&ssum[c * 4 + 1], ls.y); atomicAdd(&ssq[c * 4 + 1], lq.y);
    atomicAdd(&ssum[c * 4 + 2], ls.z); atomicAdd(&ssq[c * 4 + 2], lq.z);
    atomicAdd(&ssum[c * 4 + 3], ls.w); atomicAdd(&ssq[c * 4 + 3], lq.w);
    __syncthreads();
    if (threadIdx.x < 64) {
        atomicAdd(&g_stats[threadIdx.x], ssum[threadIdx.x]);
        atomicAdd(&g_stats[64 + threadIdx.x], ssq[threadIdx.x]);
    }
}

// ---------------- BN apply ----------------
__global__ __launch_bounds__(256) void bn_kernel(float* __restrict__ out,
                                                 const float* __restrict__ gamma,
                                                 const float* __restrict__ beta,
                                                 int n_nodes) {
    __shared__ float s_scale[64], s_shift[64];
    if (threadIdx.x < 64) {
        int j = threadIdx.x;
        float inv_n = 1.f / (float)n_nodes;
        float mu = g_stats[j] * inv_n;
        float var = g_stats[64 + j] * inv_n - mu * mu;
        if (var < 0.f) var = 0.f;
        float g = rsqrtf(var + 1e-5f) * gamma[j];
        s_scale[j] = g;
        s_shift[j] = beta[j] - mu * g;
    }
    __syncthreads();
    int total4 = n_nodes * 16;
    int stride = gridDim.x * blockDim.x;
    for (int i = blockIdx.x * blockDim.x + threadIdx.x; i < total4; i += stride) {
        float4 v = reinterpret_cast<float4*>(out)[i];
        int j0 = (i & 15) << 2;
        v.x = v.x * s_scale[j0 + 0] + s_shift[j0 + 0];
        v.y = v.y * s_scale[j0 + 1] + s_shift[j0 + 1];
        v.z = v.z * s_scale[j0 + 2] + s_shift[j0 + 2];
        v.w = v.w * s_scale[j0 + 3] + s_shift[j0 + 3];
        reinterpret_cast<float4*>(out)[i] = v;
    }
}

// ---------------- launch ----------------
extern "C" void kernel_launch(void* const* d_in, const int* in_sizes, int n_in,
                              void* d_out, int out_size) {
    const int*   src   = (const int*)d_in[0];
    const int*   dst   = (const int*)d_in[1];
    const float* x     = (const float*)d_in[2];
    const float* fc_w  = (const float*)d_in[3];
    const float* fc_b  = (const float*)d_in[4];
    const float* w1    = (const float*)d_in[5];
    const float* b1    = (const float*)d_in[6];
    const float* w2    = (const float*)d_in[7];
    const float* b2    = (const float*)d_in[8];
    const float* gamma = (const float*)d_in[9];
    const float* beta  = (const float*)d_in[10];
    float* out = (float*)d_out;

    int n_edges = in_sizes[0];
    int n_nodes = in_sizes[2] / 128;

    zero_all_kernel<<<(n_nodes + 255) / 256, 256>>>(n_nodes);
    degree_kernel<<<(n_edges + 255) / 256, 256>>>(src, dst, n_edges);

    int scan_blocks = (n_nodes + 1023) / 1024;
    scan_block_kernel<<<scan_blocks, 1024>>>(n_nodes);
    scan_spine_kernel<<<1, 32>>>(scan_blocks);
    finalize_kernel<<<(n_nodes + 255) / 256, 256>>>(n_nodes);
    bin_kernel<<<(n_edges + 255) / 256, 256>>>(src, dst, n_edges);

    int gblocks = (n_nodes + 127) / 128;
    fc_kernel<<<gblocks, 256>>>(x, fc_w, fc_b, n_nodes);

    gemm1_kernel<<<gblocks, 256>>>(w1, n_nodes);
    agg1_kernel<<<(n_nodes + 15) / 16, 256>>>(n_nodes);

    gemm2_fused_kernel<<<gblocks, 256>>>(b1, w2, n_nodes);
    agg2_stats_kernel<<<1184, 256>>>(b2, out, n_nodes);

    bn_kernel<<<512, 256>>>(out, gamma, beta, n_nodes);
}

// round 3
// speedup vs baseline: 1.8694x; 1.0308x over previous
#include <cuda_runtime.h>

#define NMAX 100000
#define EMAX 800000
#define HID 64

// ---------------- scratch (device globals) ----------------
__device__ float g_h0[NMAX * HID];
__device__ float g_hs[NMAX * HID];
__device__ float g_agg[NMAX * HID];
__device__ float g_h1[NMAX * HID];
__device__ int   g_deg_out[NMAX];
__device__ int   g_deg_in[NMAX];
__device__ float g_norm_out[NMAX];
__device__ float g_norm_in[NMAX];
__device__ int   g_incl[NMAX];
__device__ int   g_blocksum[128];
__device__ int   g_blockoff[128];
__device__ int   g_rowstart[NMAX];
__device__ int   g_cursor[NMAX];
__device__ int   g_csr_src[EMAX];
__device__ float g_stats[2 * HID];

__device__ __forceinline__ float scale_const() { return 0.70710678118654752440f; }

// ---------------- init ----------------
__global__ void zero_all_kernel(int n_nodes) {
    int idx = blockIdx.x * blockDim.x + threadIdx.x;
    if (idx < n_nodes) { g_deg_out[idx] = 0; g_deg_in[idx] = 0; }
    if (idx < 2 * HID) g_stats[idx] = 0.f;
}

__global__ void degree_kernel(const int* __restrict__ src, const int* __restrict__ dst, int n_edges) {
    int e = blockIdx.x * blockDim.x + threadIdx.x;
    if (e < n_edges) {
        atomicAdd(&g_deg_out[src[e]], 1);
        atomicAdd(&g_deg_in[dst[e]], 1);
    }
}

// ---------------- CSR build: scan of deg_in (warp-shuffle scans) ----------------
__global__ __launch_bounds__(1024) void scan_block_kernel(int n_nodes) {
    int gid = blockIdx.x * 1024 + threadIdx.x;
    int lane = threadIdx.x & 31, warp = threadIdx.x >> 5;
    int x = (gid < n_nodes) ? g_deg_in[gid] : 0;
    // inclusive warp scan
    #pragma unroll
    for (int off = 1; off < 32; off <<= 1) {
        int t = __shfl_up_sync(0xFFFFFFFFu, x, off);
        if (lane >= off) x += t;
    }
    __shared__ int wsum[32];
    if (lane == 31) wsum[warp] = x;
    __syncthreads();
    if (warp == 0) {
        int y = wsum[lane];
        #pragma unroll
        for (int off = 1; off < 32; off <<= 1) {
            int t = __shfl_up_sync(0xFFFFFFFFu, y, off);
            if (lane >= off) y += t;
        }
        wsum[lane] = y;
    }
    __syncthreads();
    if (warp > 0) x += wsum[warp - 1];
    if (gid < n_nodes) g_incl[gid] = x;
    if (threadIdx.x == 1023) g_blocksum[blockIdx.x] = x;
}

__global__ __launch_bounds__(128) void scan_spine_kernel(int n_blocks) {
    int lane = threadIdx.x & 31, warp = threadIdx.x >> 5;
    int v = (threadIdx.x < n_blocks) ? g_blocksum[threadIdx.x] : 0;
    int x = v;
    #pragma unroll
    for (int off = 1; off < 32; off <<= 1) {
        int t = __shfl_up_sync(0xFFFFFFFFu, x, off);
        if (lane >= off) x += t;
    }
    __shared__ int wsum[4];
    if (lane == 31) wsum[warp] = x;
    __syncthreads();
    int add = 0;
    #pragma unroll
    for (int w = 0; w < 3; w++) if (warp > w) add += wsum[w];
    x += add;
    if (threadIdx.x < n_blocks) g_blockoff[threadIdx.x] = x - v;  // exclusive
}

__global__ void finalize_kernel(int n_nodes) {
    int n = blockIdx.x * blockDim.x + threadIdx.x;
    if (n < n_nodes) {
        int deg = g_deg_in[n];
        int incl = g_incl[n] + g_blockoff[n >> 10];
        int start = incl - deg;
        g_rowstart[n] = start;
        g_cursor[n] = start;
        int dov = g_deg_out[n]; if (dov < 1) dov = 1;
        int din = deg; if (din < 1) din = 1;
        g_norm_out[n] = rsqrtf((float)dov);
        g_norm_in[n]  = rsqrtf((float)din);
    }
}

__global__ void bin_kernel(const int* __restrict__ src, const int* __restrict__ dst, int n_edges) {
    int e = blockIdx.x * blockDim.x + threadIdx.x;
    if (e < n_edges) {
        int p = atomicAdd(&g_cursor[dst[e]], 1);
        g_csr_src[p] = src[e];
    }
}

// ---------------- fc GEMM: h0 = x @ fc_w + fc_b  (K=128) ----------------
__global__ __launch_bounds__(256) void fc_kernel(const float* __restrict__ x,
                                                 const float* __restrict__ w,
                                                 const float* __restrict__ b,
                                                 int n_nodes) {
    __shared__ float sA[128][68];
    __shared__ float sW[64][64];
    int br = blockIdx.x * 128;
    int tx = threadIdx.x & 15, ty = threadIdx.x >> 4;
    int r0 = ty * 8, j0 = tx * 4;
    float4 acc[8];
    #pragma unroll
    for (int i = 0; i < 8; i++) acc[i] = make_float4(0.f, 0.f, 0.f, 0.f);

    for (int kc = 0; kc < 2; kc++) {
        if (kc) __syncthreads();
        for (int i = threadIdx.x; i < 1024; i += 256) {
            int k = i >> 4, c = (i & 15) << 2;
            *(float4*)&sW[k][c] = *(const float4*)&w[(kc * 64 + k) * 64 + c];
        }
        for (int i = threadIdx.x; i < 2048; i += 256) {
            int r = i >> 4, c4 = i & 15;
            int row = br + r;
            float4 v = make_float4(0.f, 0.f, 0.f, 0.f);
            if (row < n_nodes) v = *(const float4*)&x[row * 128 + kc * 64 + (c4 << 2)];
            *(float4*)&sA[r][c4 << 2] = v;
        }
        __syncthreads();
        #pragma unroll 8
        for (int k = 0; k < 64; k++) {
            float4 wv = *(float4*)&sW[k][j0];
            #pragma unroll
            for (int i = 0; i < 8; i++) {
                float a = sA[r0 + i][k];
                acc[i].x = fmaf(a, wv.x, acc[i].x);
                acc[i].y = fmaf(a, wv.y, acc[i].y);
                acc[i].z = fmaf(a, wv.z, acc[i].z);
                acc[i].w = fmaf(a, wv.w, acc[i].w);
            }
        }
    }
    float4 bv = *(const float4*)&b[j0];
    #pragma unroll
    for (int i = 0; i < 8; i++) {
        int row = br + r0 + i;
        if (row < n_nodes) {
            float4 o;
            o.x = acc[i].x + bv.x; o.y = acc[i].y + bv.y;
            o.z = acc[i].z + bv.z; o.w = acc[i].w + bv.w;
            *(float4*)&g_h0[row * 64 + j0] = o;
        }
    }
}

// ---------------- gemm1: hs = (h0 @ w1) * norm_out  (K=64) ----------------
__global__ __launch_bounds__(256) void gemm1_kernel(const float* __restrict__ w1, int n_nodes) {
    __shared__ float sA[128][68];
    __shared__ float sW[64][64];
    int br = blockIdx.x * 128;
    int tx = threadIdx.x & 15, ty = threadIdx.x >> 4;
    int r0 = ty * 8, j0 = tx * 4;

    for (int i = threadIdx.x; i < 1024; i += 256) {
        int k = i >> 4, c = (i & 15) << 2;
        *(float4*)&sW[k][c] = *(const float4*)&w1[k * 64 + c];
    }
    for (int i = threadIdx.x; i < 2048; i += 256) {
        int r = i >> 4, c4 = i & 15;
        int row = br + r;
        float4 v = make_float4(0.f, 0.f, 0.f, 0.f);
        if (row < n_nodes) v = *(const float4*)&g_h0[row * 64 + (c4 << 2)];
        *(float4*)&sA[r][c4 << 2] = v;
    }
    __syncthreads();

    float4 acc[8];
    #pragma unroll
    for (int i = 0; i < 8; i++) acc[i] = make_float4(0.f, 0.f, 0.f, 0.f);
    #pragma unroll 8
    for (int k = 0; k < 64; k++) {
        float4 wv = *(float4*)&sW[k][j0];
        #pragma unroll
        for (int i = 0; i < 8; i++) {
            float a = sA[r0 + i][k];
            acc[i].x = fmaf(a, wv.x, acc[i].x);
            acc[i].y = fmaf(a, wv.y, acc[i].y);
            acc[i].z = fmaf(a, wv.z, acc[i].z);
            acc[i].w = fmaf(a, wv.w, acc[i].w);
        }
    }
    #pragma unroll
    for (int i = 0; i < 8; i++) {
        int row = br + r0 + i;
        if (row < n_nodes) {
            float ns = g_norm_out[row];
            float4 o;
            o.x = acc[i].x * ns; o.y = acc[i].y * ns;
            o.z = acc[i].z * ns; o.w = acc[i].w * ns;
            *(float4*)&g_hs[row * 64 + j0] = o;
        }
    }
}

// ---------------- layer-1 aggregation (gather, 4x edge unroll) ----------------
__global__ __launch_bounds__(256) void agg1_kernel(int n_nodes) {
    int node = blockIdx.x * 16 + (threadIdx.x >> 4);
    int c = threadIdx.x & 15;
    if (node >= n_nodes) return;
    int beg = g_rowstart[node];
    int end = beg + g_deg_in[node];
    float4 a0 = make_float4(0.f, 0.f, 0.f, 0.f);
    float4 a1 = make_float4(0.f, 0.f, 0.f, 0.f);
    const float4* __restrict__ hs4 = reinterpret_cast<const float4*>(g_hs);
    int e = beg;
    for (; e + 4 <= end; e += 4) {
        int s0 = g_csr_src[e], s1 = g_csr_src[e + 1];
        int s2 = g_csr_src[e + 2], s3 = g_csr_src[e + 3];
        float4 v0 = hs4[s0 * 16 + c];
        float4 v1 = hs4[s1 * 16 + c];
        float4 v2 = hs4[s2 * 16 + c];
        float4 v3 = hs4[s3 * 16 + c];
        a0.x += v0.x; a0.y += v0.y; a0.z += v0.z; a0.w += v0.w;
        a1.x += v1.x; a1.y += v1.y; a1.z += v1.z; a1.w += v1.w;
        a0.x += v2.x; a0.y += v2.y; a0.z += v2.z; a0.w += v2.w;
        a1.x += v3.x; a1.y += v3.y; a1.z += v3.z; a1.w += v3.w;
    }
    for (; e < end; e++) {
        int s = g_csr_src[e];
        float4 v = hs4[s * 16 + c];
        a0.x += v.x; a0.y += v.y; a0.z += v.z; a0.w += v.w;
    }
    float ni = g_norm_in[node];
    float4 o;
    o.x = (a0.x + a1.x) * ni; o.y = (a0.y + a1.y) * ni;
    o.z = (a0.z + a1.z) * ni; o.w = (a0.w + a1.w) * ni;
    reinterpret_cast<float4*>(g_agg)[node * 16 + c] = o;
}

// ---------------- fused layer-1 epilogue + gemm2 ----------------
__global__ __launch_bounds__(256) void gemm2_fused_kernel(const float* __restrict__ b1,
                                                          const float* __restrict__ w2,
                                                          int n_nodes) {
    __shared__ float sA[128][68];
    __shared__ float sW[64][64];
    int br = blockIdx.x * 128;
    int tx = threadIdx.x & 15, ty = threadIdx.x >> 4;
    int r0 = ty * 8, j0 = tx * 4;
    const float sc = scale_const();

    for (int i = threadIdx.x; i < 1024; i += 256) {
        int k = i >> 4, c = (i & 15) << 2;
        *(float4*)&sW[k][c] = *(const float4*)&w2[k * 64 + c];
    }
    for (int i = threadIdx.x; i < 2048; i += 256) {
        int r = i >> 4, c4 = i & 15;
        int row = br + r;
        float4 v = make_float4(0.f, 0.f, 0.f, 0.f);
        if (row < n_nodes) {
            float4 h0v = *(const float4*)&g_h0[row * 64 + (c4 << 2)];
            float4 ag  = *(const float4*)&g_agg[row * 64 + (c4 << 2)];
            float4 bv  = *(const float4*)&b1[(c4 << 2)];
            v.x = (h0v.x + ag.x + bv.x) * sc;
            v.y = (h0v.y + ag.y + bv.y) * sc;
            v.z = (h0v.z + ag.z + bv.z) * sc;
            v.w = (h0v.w + ag.w + bv.w) * sc;
            *(float4*)&g_h1[row * 64 + (c4 << 2)] = v;
        }
        *(float4*)&sA[r][c4 << 2] = v;
    }
    __syncthreads();

    float4 acc[8];
    #pragma unroll
    for (int i = 0; i < 8; i++) acc[i] = make_float4(0.f, 0.f, 0.f, 0.f);
    #pragma unroll 8
    for (int k = 0; k < 64; k++) {
        float4 wv = *(float4*)&sW[k][j0];
        #pragma unroll
        for (int i = 0; i < 8; i++) {
            float a = sA[r0 + i][k];
            acc[i].x = fmaf(a, wv.x, acc[i].x);
            acc[i].y = fmaf(a, wv.y, acc[i].y);
            acc[i].z = fmaf(a, wv.z, acc[i].z);
            acc[i].w = fmaf(a, wv.w, acc[i].w);
        }
    }
    #pragma unroll
    for (int i = 0; i < 8; i++) {
        int row = br + r0 + i;
        if (row < n_nodes) {
            float ns = g_norm_out[row];
            float4 o;
            o.x = acc[i].x * ns; o.y = acc[i].y * ns;
            o.z = acc[i].z * ns; o.w = acc[i].w * ns;
            *(float4*)&g_hs[row * 64 + j0] = o;
        }
    }
}

// ---------------- fused layer-2 aggregation + epilogue + BN stats ----------------
__global__ __launch_bounds__(256) void agg2_stats_kernel(const float* __restrict__ b2,
                                                         float* __restrict__ out,
                                                         int n_nodes) {
    __shared__ float ssum[64], ssq[64];
    if (threadIdx.x < 64) { ssum[threadIdx.x] = 0.f; ssq[threadIdx.x] = 0.f; }
    __syncthreads();
    int c = threadIdx.x & 15;
    float4 bv = reinterpret_cast<const float4*>(b2)[c];
    const float sc = scale_const();
    float4 ls = make_float4(0.f, 0.f, 0.f, 0.f);
    float4 lq = make_float4(0.f, 0.f, 0.f, 0.f);
    const float4* __restrict__ hs4 = reinterpret_cast<const float4*>(g_hs);

    for (int node = blockIdx.x * 16 + (threadIdx.x >> 4); node < n_nodes; node += gridDim.x * 16) {
        int beg = g_rowstart[node];
        int end = beg + g_deg_in[node];
        float4 a0 = make_float4(0.f, 0.f, 0.f, 0.f);
        float4 a1 = make_float4(0.f, 0.f, 0.f, 0.f);
        int e = beg;
        for (; e + 4 <= end; e += 4) {
            int s0 = g_csr_src[e], s1 = g_csr_src[e + 1];
            int s2 = g_csr_src[e + 2], s3 = g_csr_src[e + 3];
            float4 v0 = hs4[s0 * 16 + c];
            float4 v1 = hs4[s1 * 16 + c];
            float4 v2 = hs4[s2 * 16 + c];
            float4 v3 = hs4[s3 * 16 + c];
            a0.x += v0.x; a0.y += v0.y; a0.z += v0.z; a0.w += v0.w;
            a1.x += v1.x; a1.y += v1.y; a1.z += v1.z; a1.w += v1.w;
            a0.x += v2.x; a0.y += v2.y; a0.z += v2.z; a0.w += v2.w;
            a1.x += v3.x; a1.y += v3.y; a1.z += v3.z; a1.w += v3.w;
        }
        for (; e < end; e++) {
            int s = g_csr_src[e];
            float4 v = hs4[s * 16 + c];
            a0.x += v.x; a0.y += v.y; a0.z += v.z; a0.w += v.w;
        }
        float ni = g_norm_in[node];
        float4 h1v = reinterpret_cast<const float4*>(g_h1)[node * 16 + c];
        float4 h2;
        h2.x = (h1v.x + (a0.x + a1.x) * ni + bv.x) * sc;
        h2.y = (h1v.y + (a0.y + a1.y) * ni + bv.y) * sc;
        h2.z = (h1v.z + (a0.z + a1.z) * ni + bv.z) * sc;
        h2.w = (h1v.w + (a0.w + a1.w) * ni + bv.w) * sc;
        reinterpret_cast<float4*>(out)[node * 16 + c] = h2;
        ls.x += h2.x; ls.y += h2.y; ls.z += h2.z; ls.w += h2.w;
        lq.x += h2.x * h2.x; lq.y += h2.y * h2.y; lq.z += h2.z * h2.z; lq.w += h2.w * h2.w;
    }
    atomicAdd(&ssum[c * 4 + 0], ls.x); atomicAdd(&ssq[c * 4 + 0], lq.x);
    atomicAdd(&ssum[c * 4 + 1], ls.y); atomicAdd(&ssq[c * 4 + 1], lq.y);
    atomicAdd(&ssum[c * 4 + 2], ls.z); atomicAdd(&ssq[c * 4 + 2], lq.z);
    atomicAdd(&ssum[c * 4 + 3], ls.w); atomicAdd(&ssq[c * 4 + 3], lq.w);
    __syncthreads();
    if (threadIdx.x < 64) {
        atomicAdd(&g_stats[threadIdx.x], ssum[threadIdx.x]);
        atomicAdd(&g_stats[64 + threadIdx.x], ssq[threadIdx.x]);
    }
}

// ---------------- BN apply ----------------
__global__ __launch_bounds__(256) void bn_kernel(float* __restrict__ out,
                                                 const float* __restrict__ gamma,
                                                 const float* __restrict__ beta,
                                                 int n_nodes) {
    __shared__ float s_scale[64], s_shift[64];
    if (threadIdx.x < 64) {
        int j = threadIdx.x;
        float inv_n = 1.f / (float)n_nodes;
        float mu = g_stats[j] * inv_n;
        float var = g_stats[64 + j] * inv_n - mu * mu;
        if (var < 0.f) var = 0.f;
        float g = rsqrtf(var + 1e-5f) * gamma[j];
        s_scale[j] = g;
        s_shift[j] = beta[j] - mu * g;
    }
    __syncthreads();
    int total4 = n_nodes * 16;
    int stride = gridDim.x * blockDim.x;
    for (int i = blockIdx.x * blockDim.x + threadIdx.x; i < total4; i += stride) {
        float4 v = reinterpret_cast<float4*>(out)[i];
        int j0 = (i & 15) << 2;
        v.x = v.x * s_scale[j0 + 0] + s_shift[j0 + 0];
        v.y = v.y * s_scale[j0 + 1] + s_shift[j0 + 1];
        v.z = v.z * s_scale[j0 + 2] + s_shift[j0 + 2];
        v.w = v.w * s_scale[j0 + 3] + s_shift[j0 + 3];
        reinterpret_cast<float4*>(out)[i] = v;
    }
}

// ---------------- launch ----------------
extern "C" void kernel_launch(void* const* d_in, const int* in_sizes, int n_in,
                              void* d_out, int out_size) {
    const int*   src   = (const int*)d_in[0];
    const int*   dst   = (const int*)d_in[1];
    const float* x     = (const float*)d_in[2];
    const float* fc_w  = (const float*)d_in[3];
    const float* fc_b  = (const float*)d_in[4];
    const float* w1    = (const float*)d_in[5];
    const float* b1    = (const float*)d_in[6];
    const float* w2    = (const float*)d_in[7];
    const float* b2    = (const float*)d_in[8];
    const float* gamma = (const float*)d_in[9];
    const float* beta  = (const float*)d_in[10];
    float* out = (float*)d_out;

    int n_edges = in_sizes[0];
    int n_nodes = in_sizes[2] / 128;

    zero_all_kernel<<<(n_nodes + 255) / 256, 256>>>(n_nodes);
    degree_kernel<<<(n_edges + 255) / 256, 256>>>(src, dst, n_edges);

    int scan_blocks = (n_nodes + 1023) / 1024;
    scan_block_kernel<<<scan_blocks, 1024>>>(n_nodes);
    scan_spine_kernel<<<1, 128>>>(scan_blocks);
    finalize_kernel<<<(n_nodes + 255) / 256, 256>>>(n_nodes);
    bin_kernel<<<(n_edges + 255) / 256, 256>>>(src, dst, n_edges);

    int gblocks = (n_nodes + 127) / 128;
    fc_kernel<<<gblocks, 256>>>(x, fc_w, fc_b, n_nodes);

    gemm1_kernel<<<gblocks, 256>>>(w1, n_nodes);
    agg1_kernel<<<(n_nodes + 15) / 16, 256>>>(n_nodes);

    gemm2_fused_kernel<<<gblocks, 256>>>(b1, w2, n_nodes);
    agg2_stats_kernel<<<1184, 256>>>(b2, out, n_nodes);

    bn_kernel<<<512, 256>>>(out, gamma, beta, n_nodes);
}